// round 8
// baseline (speedup 1.0000x reference)
#include <cuda_runtime.h>

// GraphSAGE 3-layer GCN aggregator. N=100000, E=1600000, 64->64->64->40.
//
// Restructure: ((segsum(h[src]) + h) * inv) @ W^T + b
//            = (segsum(p[src])  + p) * inv + b   with p = h @ W^T
// Pipeline:
//   CSR build: deg -> 3-kernel scan -> fill (esrc grouped by dst)
//   k0: p0 = feats @ W0^T                         (gemmf)
//   g1: agg0 = self + gather(p0)
//   k1: p1 = relu(agg0*inv + b0) @ W1^T           (gemmf, fused pre-act)
//   g2: agg1 = self + gather(p1)
//   k2: p2 = relu(agg1*inv + b1) @ W2^T  (40w)
//   g3: out = (self + gather(p2))*inv + b2        (gather, fused finalize)
// Gather: LANES lanes/node, float4/lane, 4-way unrolled dependent-load loop
// (each lane redundantly loads the shared edge index -- L1 broadcast, free).

constexpr int NN = 100000;
constexpr int NE = 1600000;
constexpr int NB = (NN + 1023) / 1024;  // 98 scan blocks

__device__ float g_pA[NN * 64];
__device__ float g_pB[NN * 64];
__device__ float g_agg[NN * 64];
__device__ int   g_deg[NN];
__device__ int   g_off[NN + 1];
__device__ int   g_cur[NN];
__device__ int   g_esrc[NE];
__device__ int   g_bsum[NB];
__device__ int   g_boff[NB];

// ---------------------------------------------------------------- degrees ---
__global__ void deg_zero_k() {
    int i = blockIdx.x * 256 + threadIdx.x;
    if (i < NN) g_deg[i] = 0;
}

__global__ void deg_count_k(const int4* __restrict__ dst4) {
    int i = blockIdx.x * 256 + threadIdx.x;
    if (i < NE / 4) {
        int4 d = __ldg(&dst4[i]);
        atomicAdd(&g_deg[d.x], 1);
        atomicAdd(&g_deg[d.y], 1);
        atomicAdd(&g_deg[d.z], 1);
        atomicAdd(&g_deg[d.w], 1);
    }
}

// ------------------------------------------------------------------- scan ---
__global__ __launch_bounds__(1024) void scan_bsum_k() {
    int i = blockIdx.x * 1024 + threadIdx.x;
    int v = (i < NN) ? g_deg[i] : 0;
#pragma unroll
    for (int o = 16; o; o >>= 1) v += __shfl_down_sync(~0u, v, o);
    __shared__ int ws[32];
    if ((threadIdx.x & 31) == 0) ws[threadIdx.x >> 5] = v;
    __syncthreads();
    if (threadIdx.x < 32) {
        int s = ws[threadIdx.x];
#pragma unroll
        for (int o = 16; o; o >>= 1) s += __shfl_down_sync(~0u, s, o);
        if (threadIdx.x == 0) g_bsum[blockIdx.x] = s;
    }
}

__global__ void scan_partials_k() {  // 1 block x 128 (NB=98 <= 128)
    int t = threadIdx.x;
    int v = (t < NB) ? g_bsum[t] : 0;
    int lane = t & 31, w = t >> 5;
    int x = v;
#pragma unroll
    for (int o = 1; o < 32; o <<= 1) {
        int y = __shfl_up_sync(~0u, x, o);
        if (lane >= o) x += y;
    }
    __shared__ int wsum[4];
    if (lane == 31) wsum[w] = x;
    __syncthreads();
    int add = 0;
    for (int j = 0; j < w; j++) add += wsum[j];
    if (t < NB) g_boff[t] = x + add - v;  // exclusive
}

__global__ __launch_bounds__(1024) void scan_write_k() {
    int i = blockIdx.x * 1024 + threadIdx.x;
    int v = (i < NN) ? g_deg[i] : 0;
    int lane = threadIdx.x & 31, w = threadIdx.x >> 5;
    int x = v;
#pragma unroll
    for (int o = 1; o < 32; o <<= 1) {
        int y = __shfl_up_sync(~0u, x, o);
        if (lane >= o) x += y;
    }
    __shared__ int ws[32], sws[32];
    if (lane == 31) ws[w] = x;
    __syncthreads();
    if (threadIdx.x < 32) {
        int s = ws[threadIdx.x];
        int xx = s;
#pragma unroll
        for (int o = 1; o < 32; o <<= 1) {
            int y = __shfl_up_sync(~0u, xx, o);
            if (lane >= o) xx += y;
        }
        sws[threadIdx.x] = xx - s;  // exclusive warp prefix
    }
    __syncthreads();
    int incl = x + sws[w] + g_boff[blockIdx.x];
    int excl = incl - v;
    if (i < NN) {
        g_off[i] = excl;
        g_cur[i] = excl;
        if (i == NN - 1) g_off[NN] = incl;
    }
}

// ------------------------------------------------------------------- fill ---
__global__ void fill_k(const int4* __restrict__ src4,
                       const int4* __restrict__ dst4) {
    int i = blockIdx.x * 256 + threadIdx.x;
    if (i < NE / 4) {
        int4 s = __ldg(&src4[i]);
        int4 d = __ldg(&dst4[i]);
        g_esrc[atomicAdd(&g_cur[d.x], 1)] = s.x;
        g_esrc[atomicAdd(&g_cur[d.y], 1)] = s.y;
        g_esrc[atomicAdd(&g_cur[d.z], 1)] = s.z;
        g_esrc[atomicAdd(&g_cur[d.w], 1)] = s.w;
    }
}

// ------------------------------------------------------------------ gemmf ---
// pout[n,o] = sum_k hrow[n,k] * W[o,k], where
//   hrow = PRE ? relu(in[n,:]*inv_n + bpre) : in[n,:]
// Block (64, 8) = 512 threads, 64 nodes per block; W in per-thread registers.
template <int DOUT, bool PRE>
__global__ __launch_bounds__(512) void gemmf_k(const float* __restrict__ in,
                                               const float* __restrict__ W,
                                               const float* __restrict__ bpre,
                                               float* __restrict__ pout) {
    __shared__ float Ws[64 * 65];
    __shared__ float hs[8][65];
    const int tx = threadIdx.x, ty = threadIdx.y;
    const int tid = ty * 64 + tx;
    for (int i = tid; i < DOUT * 64; i += 512)
        Ws[(i >> 6) * 65 + (i & 63)] = W[i];
    __syncthreads();
    float w[64];
    if (tx < DOUT) {
#pragma unroll
        for (int k = 0; k < 64; k++) w[k] = Ws[tx * 65 + k];
    }

    const int base = blockIdx.x * 64;
#pragma unroll
    for (int it = 0; it < 8; it++) {
        int n = base + it * 8 + ty;
        __syncthreads();
        if (n < NN) {
            float v = in[n * 64 + tx];
            if (PRE) {
                float inv = 1.f / (float)(__ldg(&g_off[n + 1]) - __ldg(&g_off[n]) + 1);
                v = fmaxf(fmaf(v, inv, __ldg(&bpre[tx])), 0.f);
            }
            hs[ty][tx] = v;
        }
        __syncthreads();
        if (n < NN && tx < DOUT) {
            float acc = 0.f;
#pragma unroll
            for (int k = 0; k < 64; k++) acc = fmaf(hs[ty][k], w[k], acc);
            pout[n * DOUT + tx] = acc;
        }
    }
}

// ----------------------------------------------------------------- gather ---
// agg[n,:] = pin[n,:] + sum_{e in CSR row n} pin[esrc[e],:]
// If FIN: out = agg*inv + bias (final layer, no relu).
// LANES lanes per node (L4 float4 each), GROUPS nodes per block.
// Simple dependent-load loop, 4-way unrolled (4 idx + 4 LDG.128 in flight).
template <int L4, int LANES, int GROUPS, bool FIN>
__global__ __launch_bounds__(LANES * GROUPS)
void gather_k(const float4* __restrict__ pin, float4* __restrict__ outp,
              const float4* __restrict__ bias) {
    const int tid = threadIdx.x;
    const int g = tid / LANES;
    const int q = tid % LANES;
    const int node = blockIdx.x * GROUPS + g;  // grids are exact multiples

    const int s0 = __ldg(&g_off[node]);
    const int s1 = __ldg(&g_off[node + 1]);

    float4 a0 = __ldg(&pin[node * L4 + q]);  // self term
    float4 a1 = make_float4(0.f, 0.f, 0.f, 0.f);
    float4 a2 = make_float4(0.f, 0.f, 0.f, 0.f);
    float4 a3 = make_float4(0.f, 0.f, 0.f, 0.f);

    int e = s0;
    for (; e + 3 < s1; e += 4) {
        int sa = __ldg(&g_esrc[e]);
        int sb = __ldg(&g_esrc[e + 1]);
        int sc = __ldg(&g_esrc[e + 2]);
        int sd = __ldg(&g_esrc[e + 3]);
        float4 va = __ldg(&pin[sa * L4 + q]);
        float4 vb = __ldg(&pin[sb * L4 + q]);
        float4 vc = __ldg(&pin[sc * L4 + q]);
        float4 vd = __ldg(&pin[sd * L4 + q]);
        a0.x += va.x; a0.y += va.y; a0.z += va.z; a0.w += va.w;
        a1.x += vb.x; a1.y += vb.y; a1.z += vb.z; a1.w += vb.w;
        a2.x += vc.x; a2.y += vc.y; a2.z += vc.z; a2.w += vc.w;
        a3.x += vd.x; a3.y += vd.y; a3.z += vd.z; a3.w += vd.w;
    }
    for (; e < s1; e++) {
        int sa = __ldg(&g_esrc[e]);
        float4 va = __ldg(&pin[sa * L4 + q]);
        a0.x += va.x; a0.y += va.y; a0.z += va.z; a0.w += va.w;
    }
    a0.x += a1.x + a2.x + a3.x;
    a0.y += a1.y + a2.y + a3.y;
    a0.z += a1.z + a2.z + a3.z;
    a0.w += a1.w + a2.w + a3.w;

    if (FIN) {
        float inv = 1.f / (float)(s1 - s0 + 1);
        float4 bb = __ldg(&bias[q]);
        a0.x = fmaf(a0.x, inv, bb.x);
        a0.y = fmaf(a0.y, inv, bb.y);
        a0.z = fmaf(a0.z, inv, bb.z);
        a0.w = fmaf(a0.w, inv, bb.w);
    }
    outp[node * L4 + q] = a0;
}

// ----------------------------------------------------------------- launch ---
extern "C" void kernel_launch(void* const* d_in, const int* in_sizes, int n_in,
                              void* d_out, int out_size) {
    const float* feats = (const float*)d_in[0];
    const int*   src   = (const int*)d_in[1];
    const int*   dst   = (const int*)d_in[2];
    const float* W0 = (const float*)d_in[3];
    const float* b0 = (const float*)d_in[4];
    const float* W1 = (const float*)d_in[5];
    const float* b1 = (const float*)d_in[6];
    const float* W2 = (const float*)d_in[7];
    const float* b2 = (const float*)d_in[8];
    float* out = (float*)d_out;

    void *pA_v = nullptr, *pB_v = nullptr, *agg_v = nullptr;
    cudaGetSymbolAddress(&pA_v, g_pA);
    cudaGetSymbolAddress(&pB_v, g_pB);
    cudaGetSymbolAddress(&agg_v, g_agg);
    float* pA = (float*)pA_v;
    float* pB = (float*)pB_v;
    float* agg = (float*)agg_v;

    // CSR build
    deg_zero_k<<<(NN + 255) / 256, 256>>>();
    deg_count_k<<<(NE / 4 + 255) / 256, 256>>>((const int4*)dst);
    scan_bsum_k<<<NB, 1024>>>();
    scan_partials_k<<<1, 128>>>();
    scan_write_k<<<NB, 1024>>>();
    fill_k<<<(NE / 4 + 255) / 256, 256>>>((const int4*)src, (const int4*)dst);

    const int GB_G = NN / 32;        // 3125 blocks x 32 groups (exact)
    const int GB_M = (NN + 63) / 64; // 1563
    const dim3 MB(64, 8);

    // k0: p0 = feats @ W0^T
    gemmf_k<64, false><<<GB_M, MB>>>(feats, W0, nullptr, pA);
    // g1 + k1
    gather_k<16, 16, 32, false><<<GB_G, 512>>>((const float4*)pA, (float4*)agg, nullptr);
    gemmf_k<64, true><<<GB_M, MB>>>(agg, W1, b0, pB);
    // g2 + k2
    gather_k<16, 16, 32, false><<<GB_G, 512>>>((const float4*)pB, (float4*)agg, nullptr);
    gemmf_k<40, true><<<GB_M, MB>>>(agg, W2, b1, pA);
    // g3 (fused finalize) -> out, 10 lanes/node (no dead lanes)
    gather_k<10, 10, 32, true><<<GB_G, 320>>>((const float4*)pA, (float4*)out,
                                              (const float4*)b2);
}

// round 10
// speedup vs baseline: 1.3774x; 1.3774x over previous
#include <cuda_runtime.h>

// GraphSAGE 3-layer GCN aggregator. N=100000, E=1600000, 64->64->64->40.
//
// Restructure: ((segsum(h[src]) + h) * inv) @ W^T + b
//            = (segsum(p[src])  + p) * inv + b   with p = h @ W^T
// Pipeline (Round-3 fused skeleton):
//   CSR build: deg -> 3-kernel scan -> fill (esrc grouped by dst)
//   k0: p0 = feats @ W0^T
//   k1: h1 = relu((gather p0 + self)*inv + b0); p1 = h1 @ W1^T   (fused)
//   k2: h2 = relu((gather p1 + self)*inv + b1); p2 = h2 @ W2^T   (fused)
//   k3: out = (gather p2 + self)*inv + b2
// layer_k: 16 lanes/node gather (float4/lane, 4-way unrolled), h staged in
// smem, projection with float4 LDS on 68-float-padded rows (conflict-free).

constexpr int NN = 100000;
constexpr int NE = 1600000;
constexpr int NB = (NN + 1023) / 1024;  // 98 scan blocks

__device__ float g_pA[NN * 64];
__device__ float g_pB[NN * 64];
__device__ int   g_deg[NN];
__device__ int   g_off[NN + 1];
__device__ int   g_cur[NN];
__device__ int   g_esrc[NE];
__device__ int   g_bsum[NB];
__device__ int   g_boff[NB];

// ---------------------------------------------------------------- degrees ---
__global__ void deg_zero_k() {
    int i = blockIdx.x * 256 + threadIdx.x;
    if (i < NN) g_deg[i] = 0;
}

__global__ void deg_count_k(const int4* __restrict__ dst4) {
    int i = blockIdx.x * 256 + threadIdx.x;
    if (i < NE / 4) {
        int4 d = __ldg(&dst4[i]);
        atomicAdd(&g_deg[d.x], 1);
        atomicAdd(&g_deg[d.y], 1);
        atomicAdd(&g_deg[d.z], 1);
        atomicAdd(&g_deg[d.w], 1);
    }
}

// ------------------------------------------------------------------- scan ---
__global__ __launch_bounds__(1024) void scan_bsum_k() {
    int i = blockIdx.x * 1024 + threadIdx.x;
    int v = (i < NN) ? g_deg[i] : 0;
#pragma unroll
    for (int o = 16; o; o >>= 1) v += __shfl_down_sync(~0u, v, o);
    __shared__ int ws[32];
    if ((threadIdx.x & 31) == 0) ws[threadIdx.x >> 5] = v;
    __syncthreads();
    if (threadIdx.x < 32) {
        int s = ws[threadIdx.x];
#pragma unroll
        for (int o = 16; o; o >>= 1) s += __shfl_down_sync(~0u, s, o);
        if (threadIdx.x == 0) g_bsum[blockIdx.x] = s;
    }
}

__global__ void scan_partials_k() {  // 1 block x 128 (NB=98 <= 128)
    int t = threadIdx.x;
    int v = (t < NB) ? g_bsum[t] : 0;
    int lane = t & 31, w = t >> 5;
    int x = v;
#pragma unroll
    for (int o = 1; o < 32; o <<= 1) {
        int y = __shfl_up_sync(~0u, x, o);
        if (lane >= o) x += y;
    }
    __shared__ int wsum[4];
    if (lane == 31) wsum[w] = x;
    __syncthreads();
    int add = 0;
    for (int j = 0; j < w; j++) add += wsum[j];
    if (t < NB) g_boff[t] = x + add - v;  // exclusive
}

__global__ __launch_bounds__(1024) void scan_write_k() {
    int i = blockIdx.x * 1024 + threadIdx.x;
    int v = (i < NN) ? g_deg[i] : 0;
    int lane = threadIdx.x & 31, w = threadIdx.x >> 5;
    int x = v;
#pragma unroll
    for (int o = 1; o < 32; o <<= 1) {
        int y = __shfl_up_sync(~0u, x, o);
        if (lane >= o) x += y;
    }
    __shared__ int ws[32], sws[32];
    if (lane == 31) ws[w] = x;
    __syncthreads();
    if (threadIdx.x < 32) {
        int s = ws[threadIdx.x];
        int xx = s;
#pragma unroll
        for (int o = 1; o < 32; o <<= 1) {
            int y = __shfl_up_sync(~0u, xx, o);
            if (lane >= o) xx += y;
        }
        sws[threadIdx.x] = xx - s;  // exclusive warp prefix
    }
    __syncthreads();
    int incl = x + sws[w] + g_boff[blockIdx.x];
    int excl = incl - v;
    if (i < NN) {
        g_off[i] = excl;
        g_cur[i] = excl;
        if (i == NN - 1) g_off[NN] = incl;
    }
}

// ------------------------------------------------------------------- fill ---
__global__ void fill_k(const int4* __restrict__ src4,
                       const int4* __restrict__ dst4) {
    int i = blockIdx.x * 256 + threadIdx.x;
    if (i < NE / 4) {
        int4 s = __ldg(&src4[i]);
        int4 d = __ldg(&dst4[i]);
        g_esrc[atomicAdd(&g_cur[d.x], 1)] = s.x;
        g_esrc[atomicAdd(&g_cur[d.y], 1)] = s.y;
        g_esrc[atomicAdd(&g_cur[d.z], 1)] = s.z;
        g_esrc[atomicAdd(&g_cur[d.w], 1)] = s.w;
    }
}

// ------------------------------------------------------------------- gemm ---
// p[n,o] = sum_k h[n,k] * W[o,k]  (k0: initial projection of raw features)
__global__ __launch_bounds__(512) void gemm_k(const float* __restrict__ h,
                                              const float* __restrict__ W,
                                              float* __restrict__ p) {
    __shared__ float Ws[64 * 65];
    __shared__ float hs[8][64];
    const int tx = threadIdx.x, ty = threadIdx.y;
    const int tid = ty * 64 + tx;
    for (int i = tid; i < 64 * 64; i += 512)
        Ws[(i >> 6) * 65 + (i & 63)] = W[i];
    __syncthreads();
    float w[64];
#pragma unroll
    for (int k = 0; k < 64; k++) w[k] = Ws[tx * 65 + k];

    const int base = blockIdx.x * 64;
#pragma unroll
    for (int it = 0; it < 8; it++) {
        int n = base + it * 8 + ty;
        __syncthreads();
        if (n < NN) hs[ty][tx] = h[n * 64 + tx];
        __syncthreads();
        if (n < NN) {
            float acc = 0.f;
#pragma unroll
            for (int k = 0; k < 64; k++) acc = fmaf(hs[ty][k], w[k], acc);
            p[n * 64 + tx] = acc;
        }
    }
}

// ---------------------------------------------------------- fused layer -----
// Per node: gather-sum p[src] rows (CSR), + self, *inv, +b, (relu),
// then optionally project h @ W^T -> pout (width DO). If DO==0, write h
// (width DG) straight to pout. 256 threads = 16 node-groups x 16 lanes.
// Rows padded to 68 floats (272B): 16B-aligned, conflict-free LDS.128.
template <int DG, int DO, bool RELU>
__global__ __launch_bounds__(256) void layer_k(const float* __restrict__ bv,
                                               const float* __restrict__ W,
                                               const float* __restrict__ pin,
                                               float* __restrict__ pout) {
    constexpr int L4 = DG / 4;
    __shared__ __align__(16) float Ws[(DO > 0 ? DO : 1) * 68];
    __shared__ __align__(16) float hs[16][68];
    const int tid = threadIdx.x;

    if (DO > 0) {
        for (int i = tid; i < DO * 64; i += 256)
            Ws[(i >> 6) * 68 + (i & 63)] = W[i];
    }

    const int g = tid >> 4;
    const int q = tid & 15;
    const int node = blockIdx.x * 16 + g;  // grid exact: 6250*16 = 100000
    const float4* pin4 = reinterpret_cast<const float4*>(pin);

    if (q < L4) {
        const int s0 = __ldg(&g_off[node]);
        const int s1 = __ldg(&g_off[node + 1]);
        float inv = 1.f / (float)(s1 - s0 + 1);

        float4 a0 = __ldg(&pin4[node * L4 + q]);  // self term
        float4 a1 = make_float4(0.f, 0.f, 0.f, 0.f);
        float4 a2 = make_float4(0.f, 0.f, 0.f, 0.f);
        float4 a3 = make_float4(0.f, 0.f, 0.f, 0.f);

        int e = s0;
        for (; e + 3 < s1; e += 4) {
            int sa = __ldg(&g_esrc[e]);
            int sb = __ldg(&g_esrc[e + 1]);
            int sc = __ldg(&g_esrc[e + 2]);
            int sd = __ldg(&g_esrc[e + 3]);
            float4 va = __ldg(&pin4[sa * L4 + q]);
            float4 vb = __ldg(&pin4[sb * L4 + q]);
            float4 vc = __ldg(&pin4[sc * L4 + q]);
            float4 vd = __ldg(&pin4[sd * L4 + q]);
            a0.x += va.x; a0.y += va.y; a0.z += va.z; a0.w += va.w;
            a1.x += vb.x; a1.y += vb.y; a1.z += vb.z; a1.w += vb.w;
            a2.x += vc.x; a2.y += vc.y; a2.z += vc.z; a2.w += vc.w;
            a3.x += vd.x; a3.y += vd.y; a3.z += vd.z; a3.w += vd.w;
        }
        for (; e < s1; e++) {
            int sa = __ldg(&g_esrc[e]);
            float4 va = __ldg(&pin4[sa * L4 + q]);
            a0.x += va.x; a0.y += va.y; a0.z += va.z; a0.w += va.w;
        }
        a0.x += a1.x + a2.x; a0.y += a1.y + a2.y;
        a0.z += a1.z + a2.z; a0.w += a1.w + a2.w;
        a0.x += a3.x; a0.y += a3.y; a0.z += a3.z; a0.w += a3.w;

        float4 bb = __ldg(&reinterpret_cast<const float4*>(bv)[q]);
        float4 r;
        r.x = fmaf(a0.x, inv, bb.x);
        r.y = fmaf(a0.y, inv, bb.y);
        r.z = fmaf(a0.z, inv, bb.z);
        r.w = fmaf(a0.w, inv, bb.w);
        if (RELU) {
            r.x = fmaxf(r.x, 0.f); r.y = fmaxf(r.y, 0.f);
            r.z = fmaxf(r.z, 0.f); r.w = fmaxf(r.w, 0.f);
        }
        if (DO == 0) {
            reinterpret_cast<float4*>(pout)[node * L4 + q] = r;
        } else {
            reinterpret_cast<float4*>(&hs[g][0])[q] = r;
        }
    }

    if (DO > 0) {
        __syncthreads();
        constexpr int TOT = 16 * DO;
#pragma unroll
        for (int rr = 0; rr < (TOT + 255) / 256; rr++) {
            int oi = rr * 256 + tid;
            if (oi < TOT) {
                int gg = oi / DO;
                int o = oi - gg * DO;
                const float4* hrow = reinterpret_cast<const float4*>(&hs[gg][0]);
                const float4* wrow = reinterpret_cast<const float4*>(&Ws[o * 68]);
                float acc = 0.f;
#pragma unroll
                for (int k4 = 0; k4 < 16; k4++) {
                    float4 hv = hrow[k4];
                    float4 wv = wrow[k4];
                    acc = fmaf(hv.x, wv.x, acc);
                    acc = fmaf(hv.y, wv.y, acc);
                    acc = fmaf(hv.z, wv.z, acc);
                    acc = fmaf(hv.w, wv.w, acc);
                }
                int gn = blockIdx.x * 16 + gg;
                pout[gn * DO + o] = acc;
            }
        }
    }
}

// ----------------------------------------------------------------- launch ---
extern "C" void kernel_launch(void* const* d_in, const int* in_sizes, int n_in,
                              void* d_out, int out_size) {
    const float* feats = (const float*)d_in[0];
    const int*   src   = (const int*)d_in[1];
    const int*   dst   = (const int*)d_in[2];
    const float* W0 = (const float*)d_in[3];
    const float* b0 = (const float*)d_in[4];
    const float* W1 = (const float*)d_in[5];
    const float* b1 = (const float*)d_in[6];
    const float* W2 = (const float*)d_in[7];
    const float* b2 = (const float*)d_in[8];
    float* out = (float*)d_out;

    void *pA_v = nullptr, *pB_v = nullptr;
    cudaGetSymbolAddress(&pA_v, g_pA);
    cudaGetSymbolAddress(&pB_v, g_pB);
    float* pA = (float*)pA_v;
    float* pB = (float*)pB_v;

    // CSR build
    deg_zero_k<<<(NN + 255) / 256, 256>>>();
    deg_count_k<<<(NE / 4 + 255) / 256, 256>>>((const int4*)dst);
    scan_bsum_k<<<NB, 1024>>>();
    scan_partials_k<<<1, 128>>>();
    scan_write_k<<<NB, 1024>>>();
    fill_k<<<(NE / 4 + 255) / 256, 256>>>((const int4*)src, (const int4*)dst);

    const int GB_L = (NN + 15) / 16;  // 6250

    // k0: p0 = feats @ W0^T
    gemm_k<<<(NN + 63) / 64, dim3(64, 8)>>>(feats, W0, pA);
    // k1: h1 = relu(agg(p0)*inv + b0); p1 = h1 @ W1^T
    layer_k<64, 64, true><<<GB_L, 256>>>(b0, W1, pA, pB);
    // k2: h2 = relu(agg(p1)*inv + b1); p2 = h2 @ W2^T (40-wide)
    layer_k<64, 40, true><<<GB_L, 256>>>(b1, W2, pB, pA);
    // k3: out = agg(p2)*inv + b2
    layer_k<40, 0, false><<<GB_L, 256>>>(b2, nullptr, pA, out);
}

// round 11
// speedup vs baseline: 1.4846x; 1.0778x over previous
#include <cuda_runtime.h>
#include <cuda_fp16.h>

// GraphSAGE 3-layer GCN aggregator. N=100000, E=1600000, 64->64->64->40.
//
// Restructure: ((segsum(h[src]) + h) * inv) @ W^T + b
//            = (segsum(p[src])  + p) * inv + b   with p = h @ W^T
// p stored in fp16 (gather traffic halved: one 128B line per node row);
// all accumulation/weights/activations in fp32.
// Gather: ONE WARP PER NODE = 4 edge-slots x 8 column-chunks (16B/lane),
// zero intra-warp divergence, cross-slot allreduce via 2 shfl_xor per col.
// p2 (40-wide) padded to 64-wide with zeros so every gather is uniform.

constexpr int NN = 100000;
constexpr int NE = 1600000;
constexpr int NB = (NN + 1023) / 1024;  // 98 scan blocks

__device__ __half g_pA[NN * 64];
__device__ __half g_pB[NN * 64];
__device__ int    g_deg[NN];
__device__ int    g_off[NN + 1];
__device__ int    g_cur[NN];
__device__ int    g_esrc[NE];
__device__ int    g_bsum[NB];

// ---------------------------------------------------------------- degrees ---
__global__ void deg_zero_k() {
    int i = blockIdx.x * 256 + threadIdx.x;
    if (i < NN) g_deg[i] = 0;
}

__global__ void deg_count_k(const int4* __restrict__ dst4) {
    int i = blockIdx.x * 256 + threadIdx.x;
    if (i < NE / 4) {
        int4 d = __ldg(&dst4[i]);
        atomicAdd(&g_deg[d.x], 1);
        atomicAdd(&g_deg[d.y], 1);
        atomicAdd(&g_deg[d.z], 1);
        atomicAdd(&g_deg[d.w], 1);
    }
}

// ------------------------------------------------------------------- scan ---
__global__ __launch_bounds__(1024) void scan_bsum_k() {
    int i = blockIdx.x * 1024 + threadIdx.x;
    int v = (i < NN) ? g_deg[i] : 0;
#pragma unroll
    for (int o = 16; o; o >>= 1) v += __shfl_down_sync(~0u, v, o);
    __shared__ int ws[32];
    if ((threadIdx.x & 31) == 0) ws[threadIdx.x >> 5] = v;
    __syncthreads();
    if (threadIdx.x < 32) {
        int s = ws[threadIdx.x];
#pragma unroll
        for (int o = 16; o; o >>= 1) s += __shfl_down_sync(~0u, s, o);
        if (threadIdx.x == 0) g_bsum[blockIdx.x] = s;
    }
}

// scan_write with inlined cross-block partials (each block sums g_bsum[<bid]).
__global__ __launch_bounds__(1024) void scan_write_k() {
    const int lane = threadIdx.x & 31, w = threadIdx.x >> 5;

    // block offset = sum of g_bsum[j], j < blockIdx.x  (NB=98 <= 1024)
    int part = (threadIdx.x < blockIdx.x) ? g_bsum[threadIdx.x] : 0;
#pragma unroll
    for (int o = 16; o; o >>= 1) part += __shfl_down_sync(~0u, part, o);
    __shared__ int ws2[32];
    if (lane == 0) ws2[w] = part;
    __syncthreads();
    __shared__ int boff_s;
    if (threadIdx.x < 32) {
        int s = ws2[threadIdx.x];
#pragma unroll
        for (int o = 16; o; o >>= 1) s += __shfl_down_sync(~0u, s, o);
        if (threadIdx.x == 0) boff_s = s;
    }

    // intra-block exclusive scan of degrees
    int i = blockIdx.x * 1024 + threadIdx.x;
    int v = (i < NN) ? g_deg[i] : 0;
    int x = v;
#pragma unroll
    for (int o = 1; o < 32; o <<= 1) {
        int y = __shfl_up_sync(~0u, x, o);
        if (lane >= o) x += y;
    }
    __shared__ int ws[32], sws[32];
    if (lane == 31) ws[w] = x;
    __syncthreads();
    if (threadIdx.x < 32) {
        int s = ws[threadIdx.x];
        int xx = s;
#pragma unroll
        for (int o = 1; o < 32; o <<= 1) {
            int y = __shfl_up_sync(~0u, xx, o);
            if (lane >= o) xx += y;
        }
        sws[threadIdx.x] = xx - s;  // exclusive warp prefix
    }
    __syncthreads();
    int incl = x + sws[w] + boff_s;
    int excl = incl - v;
    if (i < NN) {
        g_off[i] = excl;
        g_cur[i] = excl;
        if (i == NN - 1) g_off[NN] = incl;
    }
}

// ------------------------------------------------------------------- fill ---
__global__ void fill_k(const int4* __restrict__ src4,
                       const int4* __restrict__ dst4) {
    int i = blockIdx.x * 256 + threadIdx.x;
    if (i < NE / 4) {
        int4 s = __ldg(&src4[i]);
        int4 d = __ldg(&dst4[i]);
        g_esrc[atomicAdd(&g_cur[d.x], 1)] = s.x;
        g_esrc[atomicAdd(&g_cur[d.y], 1)] = s.y;
        g_esrc[atomicAdd(&g_cur[d.z], 1)] = s.z;
        g_esrc[atomicAdd(&g_cur[d.w], 1)] = s.w;
    }
}

// --------------------------------------------------------------- gather -----
// uint4 = 8 halves; convert + accumulate into fp32 acc[8].
__device__ __forceinline__ void add8(float acc[8], uint4 u) {
    __half2* h = reinterpret_cast<__half2*>(&u);
#pragma unroll
    for (int j = 0; j < 4; j++) {
        float2 f = __half22float2(h[j]);
        acc[2 * j]     += f.x;
        acc[2 * j + 1] += f.y;
    }
}

// Warp-collective gather of one node's aggregated row (self + neighbors).
// es = lane>>3 (edge slot 0..3), c = lane&7 (column chunk). After the
// allreduce every lane holds the full 8-col partial for its chunk c.
__device__ __forceinline__ void gather_node(const __half* __restrict__ pin,
                                            int node, int s0, int s1,
                                            int es, int c, float acc[8]) {
#pragma unroll
    for (int j = 0; j < 8; j++) acc[j] = 0.f;
    if (es == 0)
        add8(acc, __ldg(reinterpret_cast<const uint4*>(pin + node * 64) + c));

    int e = s0;
    for (; e + 8 <= s1; e += 8) {
        int i0 = __ldg(&g_esrc[e + es]);
        int i1 = __ldg(&g_esrc[e + 4 + es]);
        uint4 u0 = __ldg(reinterpret_cast<const uint4*>(pin + i0 * 64) + c);
        uint4 u1 = __ldg(reinterpret_cast<const uint4*>(pin + i1 * 64) + c);
        add8(acc, u0);
        add8(acc, u1);
    }
    for (; e < s1; e += 4) {
        int ee = e + es;
        if (ee < s1) {
            int i0 = __ldg(&g_esrc[ee]);
            add8(acc, __ldg(reinterpret_cast<const uint4*>(pin + i0 * 64) + c));
        }
    }
#pragma unroll
    for (int j = 0; j < 8; j++) {
        acc[j] += __shfl_xor_sync(~0u, acc[j], 8);
        acc[j] += __shfl_xor_sync(~0u, acc[j], 16);
    }
}

// ------------------------------------------------------------------- gemm ---
// k0: p0 = feats @ W0^T (fp32 in, fp16 out). Block (64,8)=512thr, 64 nodes.
__global__ __launch_bounds__(512) void gemm_k(const float* __restrict__ h,
                                              const float* __restrict__ W,
                                              __half* __restrict__ p) {
    __shared__ float Ws[64 * 65];
    __shared__ float hs[8][64];
    const int tx = threadIdx.x, ty = threadIdx.y;
    const int tid = ty * 64 + tx;
    for (int i = tid; i < 64 * 64; i += 512)
        Ws[(i >> 6) * 65 + (i & 63)] = W[i];
    __syncthreads();
    float w[64];
#pragma unroll
    for (int k = 0; k < 64; k++) w[k] = Ws[tx * 65 + k];

    const int base = blockIdx.x * 64;
#pragma unroll
    for (int it = 0; it < 8; it++) {
        int n = base + it * 8 + ty;
        __syncthreads();
        if (n < NN) hs[ty][tx] = h[n * 64 + tx];
        __syncthreads();
        if (n < NN) {
            float acc = 0.f;
#pragma unroll
            for (int k = 0; k < 64; k++) acc = fmaf(hs[ty][k], w[k], acc);
            p[n * 64 + tx] = __float2half_rn(acc);
        }
    }
}

// ---------------------------------------------------------- fused layer -----
// Per warp: gather one node, epilogue relu((agg)*inv + b) -> hs; then block
// projects hs @ W^T into pout (fp16, 64-stride, zero-filled for o>=DO).
// 512 threads = 16 warps = 16 nodes/block; grid 6250 (exact).
template <int DO>
__global__ __launch_bounds__(512) void layer_k(const float* __restrict__ bv,
                                               const float* __restrict__ W,
                                               const __half* __restrict__ pin,
                                               __half* __restrict__ pout) {
    __shared__ __align__(16) float Ws[64 * 68];
    __shared__ __align__(16) float hs[16][68];
    const int tid = threadIdx.x;
    const int warp = tid >> 5, lane = tid & 31;
    const int es = lane >> 3, c = lane & 7;
    const int node = blockIdx.x * 16 + warp;

    for (int i = tid; i < DO * 64; i += 512)
        Ws[(i >> 6) * 68 + (i & 63)] = W[i];

    const int s0 = __ldg(&g_off[node]);
    const int s1 = __ldg(&g_off[node + 1]);

    float acc[8];
    gather_node(pin, node, s0, s1, es, c, acc);

    if (es == 0) {
        float inv = 1.f / (float)(s1 - s0 + 1);
        const float4* bv4 = reinterpret_cast<const float4*>(bv);
        float4 b0 = __ldg(&bv4[c * 2]);
        float4 b1 = __ldg(&bv4[c * 2 + 1]);
        float4 r0, r1;
        r0.x = fmaxf(fmaf(acc[0], inv, b0.x), 0.f);
        r0.y = fmaxf(fmaf(acc[1], inv, b0.y), 0.f);
        r0.z = fmaxf(fmaf(acc[2], inv, b0.z), 0.f);
        r0.w = fmaxf(fmaf(acc[3], inv, b0.w), 0.f);
        r1.x = fmaxf(fmaf(acc[4], inv, b1.x), 0.f);
        r1.y = fmaxf(fmaf(acc[5], inv, b1.y), 0.f);
        r1.z = fmaxf(fmaf(acc[6], inv, b1.z), 0.f);
        r1.w = fmaxf(fmaf(acc[7], inv, b1.w), 0.f);
        float4* hrow = reinterpret_cast<float4*>(&hs[warp][0]);
        hrow[c * 2]     = r0;
        hrow[c * 2 + 1] = r1;
    }
    __syncthreads();

    // projection: 16 nodes x 64 output cols (zeros for o >= DO)
#pragma unroll
    for (int rr = 0; rr < 2; rr++) {
        int oi = rr * 512 + tid;
        int gg = oi >> 6, o = oi & 63;
        float v = 0.f;
        if (DO == 64 || o < DO) {
            const float4* hrow = reinterpret_cast<const float4*>(&hs[gg][0]);
            const float4* wrow = reinterpret_cast<const float4*>(&Ws[o * 68]);
            float a = 0.f;
#pragma unroll
            for (int k4 = 0; k4 < 16; k4++) {
                float4 hv = hrow[k4];
                float4 wv = wrow[k4];
                a = fmaf(hv.x, wv.x, a);
                a = fmaf(hv.y, wv.y, a);
                a = fmaf(hv.z, wv.z, a);
                a = fmaf(hv.w, wv.w, a);
            }
            v = a;
        }
        pout[(blockIdx.x * 16 + gg) * 64 + o] = __float2half_rn(v);
    }
}

// ------------------------------------------------------------- final layer --
// out = (gather p2 + self)*inv + b2, 40 cols (chunks 5..7 of p2 are zeros).
// 256 threads = 8 warps = 8 nodes/block; grid 12500 (exact).
__global__ __launch_bounds__(256) void fin_k(const float* __restrict__ bv,
                                             const __half* __restrict__ pin,
                                             float* __restrict__ out) {
    const int tid = threadIdx.x;
    const int warp = tid >> 5, lane = tid & 31;
    const int es = lane >> 3, c = lane & 7;
    const int node = blockIdx.x * 8 + warp;

    const int s0 = __ldg(&g_off[node]);
    const int s1 = __ldg(&g_off[node + 1]);

    float acc[8];
    gather_node(pin, node, s0, s1, es, c, acc);

    if (es == 0 && c < 5) {
        float inv = 1.f / (float)(s1 - s0 + 1);
        const float4* bv4 = reinterpret_cast<const float4*>(bv);
        float4 b0 = __ldg(&bv4[c * 2]);
        float4 b1 = __ldg(&bv4[c * 2 + 1]);
        float4 r0, r1;
        r0.x = fmaf(acc[0], inv, b0.x);
        r0.y = fmaf(acc[1], inv, b0.y);
        r0.z = fmaf(acc[2], inv, b0.z);
        r0.w = fmaf(acc[3], inv, b0.w);
        r1.x = fmaf(acc[4], inv, b1.x);
        r1.y = fmaf(acc[5], inv, b1.y);
        r1.z = fmaf(acc[6], inv, b1.z);
        r1.w = fmaf(acc[7], inv, b1.w);
        float4* out4 = reinterpret_cast<float4*>(out);
        out4[node * 10 + c * 2]     = r0;
        out4[node * 10 + c * 2 + 1] = r1;
    }
}

// ----------------------------------------------------------------- launch ---
extern "C" void kernel_launch(void* const* d_in, const int* in_sizes, int n_in,
                              void* d_out, int out_size) {
    const float* feats = (const float*)d_in[0];
    const int*   src   = (const int*)d_in[1];
    const int*   dst   = (const int*)d_in[2];
    const float* W0 = (const float*)d_in[3];
    const float* b0 = (const float*)d_in[4];
    const float* W1 = (const float*)d_in[5];
    const float* b1 = (const float*)d_in[6];
    const float* W2 = (const float*)d_in[7];
    const float* b2 = (const float*)d_in[8];
    float* out = (float*)d_out;

    void *pA_v = nullptr, *pB_v = nullptr;
    cudaGetSymbolAddress(&pA_v, g_pA);
    cudaGetSymbolAddress(&pB_v, g_pB);
    __half* pA = (__half*)pA_v;
    __half* pB = (__half*)pB_v;

    // CSR build
    deg_zero_k<<<(NN + 255) / 256, 256>>>();
    deg_count_k<<<(NE / 4 + 255) / 256, 256>>>((const int4*)dst);
    scan_bsum_k<<<NB, 1024>>>();
    scan_write_k<<<NB, 1024>>>();
    fill_k<<<(NE / 4 + 255) / 256, 256>>>((const int4*)src, (const int4*)dst);

    // k0: p0 = feats @ W0^T
    gemm_k<<<(NN + 63) / 64, dim3(64, 8)>>>(feats, W0, pA);
    // k1: h1 = relu(agg(p0)*inv + b0); p1 = h1 @ W1^T
    layer_k<64><<<NN / 16, 512>>>(b0, W1, pA, pB);
    // k2: h2 = relu(agg(p1)*inv + b1); p2 = h2 @ W2^T (40-wide, zero-padded)
    layer_k<40><<<NN / 16, 512>>>(b1, W2, pB, pA);
    // k3: out = agg(p2)*inv + b2
    fin_k<<<NN / 8, 256>>>(b2, pA, out);
}